// round 2
// baseline (speedup 1.0000x reference)
#include <cuda_runtime.h>
#include <cuda_bf16.h>

#define NN 100000
#define DD 64
#define EE 1200000

// ---------------- scratch (static device globals — allowed) ----------------
__device__ float g_deg[NN];
__device__ float g_norm[EE];
__device__ int   g_rows[EE];
__device__ int   g_cols[EE];
__device__ float g_x[NN * DD];
__device__ float g_y[NN * DD];
__device__ int   g_is64;

// ---------------- dtype detection: int64 vs int32 edge_index ----------------
// For nonnegative int64 < 2^31, every odd 32-bit word (high half) is 0.
// For int32 indices in [0,100000), 4096 sampled odd words all-zero is ~impossible.
__global__ void detect_k(const unsigned* __restrict__ w) {
    __shared__ int nz;
    if (threadIdx.x == 0) nz = 0;
    __syncthreads();
    int cnt = 0;
    const int S = 4096;
    const int stride = (2 * EE) / S;  // 585
    for (int i = threadIdx.x; i < S; i += blockDim.x) {
        long long idx = ((long long)i * stride) | 1;  // odd word, < 2*EE
        if (w[idx] != 0u) cnt++;
    }
    atomicAdd(&nz, cnt);
    __syncthreads();
    if (threadIdx.x == 0) g_is64 = (nz == 0) ? 1 : 0;
}

__device__ __forceinline__ int edge_val(const void* ei, long long idx) {
    if (g_is64) return (int)((const long long*)ei)[idx];
    return ((const int*)ei)[idx];
}

// ---------------- init: x = out = embedding, y = 0, deg = 0 ----------------
__global__ void init_k(const float* __restrict__ emb, float* __restrict__ out) {
    int i = blockIdx.x * blockDim.x + threadIdx.x;
    if (i < NN * DD) {
        float v = emb[i];
        g_x[i] = v;
        out[i] = v;
        g_y[i] = 0.0f;
    }
    if (i < NN) g_deg[i] = 0.0f;
}

// ---------------- degree of col ----------------
__global__ void deg_k(const void* __restrict__ ei) {
    int e = blockIdx.x * blockDim.x + threadIdx.x;
    if (e >= EE) return;
    int c = edge_val(ei, (long long)EE + e);
    atomicAdd(&g_deg[c], 1.0f);
}

// ---------------- per-edge prep: int32 rows/cols + norm ----------------
__global__ void prep_k(const void* __restrict__ ei) {
    int e = blockIdx.x * blockDim.x + threadIdx.x;
    if (e >= EE) return;
    int r = edge_val(ei, e);
    int c = edge_val(ei, (long long)EE + e);
    g_rows[e] = r;
    g_cols[e] = c;
    float dr = fmaxf(g_deg[r], 1.0f);
    float dc = fmaxf(g_deg[c], 1.0f);
    g_norm[e] = rsqrtf(dr * dc);
}

// ---------------- vector RED helper ----------------
__device__ __forceinline__ void red_add4(float* p, float4 m) {
#if __CUDA_ARCH__ >= 900
    atomicAdd((float4*)p, m);
#else
    atomicAdd((float2*)p, make_float2(m.x, m.y));
    atomicAdd((float2*)(p + 2), make_float2(m.z, m.w));
#endif
}

// ---------------- scatter: y[row] += norm * x[col] ----------------
// 16 threads per edge, each handles one float4 (coalesced 256B per edge).
__global__ void scatter_k() {
    long long tid = (long long)blockIdx.x * blockDim.x + threadIdx.x;
    int e = (int)(tid >> 4);
    if (e >= EE) return;
    int lane = (int)(tid & 15);
    int r = __ldg(&g_rows[e]);
    int c = __ldg(&g_cols[e]);
    float nr = __ldg(&g_norm[e]);
    const float4 v = __ldg((const float4*)&g_x[c * DD + lane * 4]);
    float4 m = make_float4(v.x * nr, v.y * nr, v.z * nr, v.w * nr);
    red_add4(&g_y[r * DD + lane * 4], m);
}

// ---------------- per-node: v = y + out; v /= ||v||; x = v; out = (out+v)*scale;
//                  re-zero y for next layer ----------------
__global__ void node_k(float* __restrict__ out, float scale) {
    int gw = (blockIdx.x * blockDim.x + threadIdx.x) >> 5;  // warp per node
    int lane = threadIdx.x & 31;
    if (gw >= NN) return;
    int base = gw * DD + lane * 2;
    float2 y = *(float2*)&g_y[base];
    float2 o = *(float2*)&out[base];
    float vx = y.x + o.x;
    float vy = y.y + o.y;
    float ss = vx * vx + vy * vy;
#pragma unroll
    for (int m = 16; m; m >>= 1) ss += __shfl_xor_sync(0xffffffffu, ss, m);
    float s = 1.0f / fmaxf(sqrtf(ss), 1e-12f);
    vx *= s;
    vy *= s;
    *(float2*)&g_x[base] = make_float2(vx, vy);
    *(float2*)&out[base] = make_float2((o.x + vx) * scale, (o.y + vy) * scale);
    *(float2*)&g_y[base] = make_float2(0.0f, 0.0f);
}

// ---------------- launch ----------------
extern "C" void kernel_launch(void* const* d_in, const int* in_sizes, int n_in,
                              void* d_out, int out_size) {
    // robust input ordering: embedding has NN*DD elements
    int ei_idx = 0, emb_idx = 1;
    if (in_sizes[0] == NN * DD) { ei_idx = 1; emb_idx = 0; }
    const void* ei = d_in[ei_idx];
    const float* emb = (const float*)d_in[emb_idx];
    float* out = (float*)d_out;

    detect_k<<<1, 256>>>((const unsigned*)ei);
    init_k<<<(NN * DD + 255) / 256, 256>>>(emb, out);
    deg_k<<<(EE + 255) / 256, 256>>>(ei);
    prep_k<<<(EE + 255) / 256, 256>>>(ei);

    const int scatter_blocks = (EE * 16 + 255) / 256;  // 75000
    const int node_blocks = (NN * 32 + 255) / 256;     // 12500
    for (int l = 0; l < 3; l++) {
        scatter_k<<<scatter_blocks, 256>>>();
        node_k<<<node_blocks, 256>>>(out, (l == 2) ? 0.25f : 1.0f);
    }
}

// round 5
// speedup vs baseline: 1.4256x; 1.4256x over previous
#include <cuda_runtime.h>
#include <cuda_bf16.h>

#define NN 100000
#define DD 64
#define EE 1200000
#define SCAN_CHUNK 1024
#define NBLK_SCAN ((NN + SCAN_CHUNK - 1) / SCAN_CHUNK)  // 98

// ---------------- scratch (static device globals — allowed) ----------------
__device__ int   g_deg[NN];      // col-degree
__device__ int   g_cnt[NN];      // row counts for CSR
__device__ int   g_rowptr[NN];   // exclusive scan of g_cnt
__device__ int   g_cursor[NN];   // placement cursors
__device__ int   g_bsum[NBLK_SCAN];
__device__ int2  g_meta[EE];     // (col, norm-bits) sorted by row
__device__ float g_x0[NN * DD];
__device__ float g_x1[NN * DD];
__device__ int   g_is64;

// ---------------- dtype detection: int64 vs int32 edge_index ----------------
// For nonnegative int64 < 2^31, every odd 32-bit word (high half) is 0.
__global__ void detect_k(const unsigned* __restrict__ w) {
    __shared__ int nz;
    if (threadIdx.x == 0) nz = 0;
    __syncthreads();
    int cnt = 0;
    const int S = 4096;
    const int stride = (2 * EE) / S;
    for (int i = threadIdx.x; i < S; i += blockDim.x) {
        long long idx = ((long long)i * stride) | 1;  // odd 32-bit word
        if (w[idx] != 0u) cnt++;
    }
    atomicAdd(&nz, cnt);
    __syncthreads();
    if (threadIdx.x == 0) g_is64 = (nz == 0) ? 1 : 0;
}

__device__ __forceinline__ int edge_val(const void* ei, long long idx) {
    if (g_is64) return (int)((const long long*)ei)[idx];
    return ((const int*)ei)[idx];
}

// ---------------- init: x0 = out = embedding; zero deg/cnt/cursor ----------------
__global__ void init_k(const float* __restrict__ emb, float* __restrict__ out) {
    int i = blockIdx.x * blockDim.x + threadIdx.x;
    if (i < NN * DD) {
        float v = emb[i];
        g_x0[i] = v;
        out[i] = v;
    }
    if (i < NN) {
        g_deg[i] = 0;
        g_cnt[i] = 0;
        g_cursor[i] = 0;
    }
}

// ---------------- histograms: col-degree + row counts ----------------
__global__ void hist_k(const void* __restrict__ ei) {
    int e = blockIdx.x * blockDim.x + threadIdx.x;
    if (e >= EE) return;
    int r = edge_val(ei, e);
    int c = edge_val(ei, (long long)EE + e);
    atomicAdd(&g_deg[c], 1);
    atomicAdd(&g_cnt[r], 1);
}

// ---------------- 3-step exclusive scan of g_cnt -> g_rowptr ----------------
__global__ void scan1_k() {
    __shared__ int sh[SCAN_CHUNK];
    int g = blockIdx.x * SCAN_CHUNK + threadIdx.x;
    int v = (g < NN) ? g_cnt[g] : 0;
    sh[threadIdx.x] = v;
    __syncthreads();
    for (int off = 1; off < SCAN_CHUNK; off <<= 1) {
        int t = (threadIdx.x >= off) ? sh[threadIdx.x - off] : 0;
        __syncthreads();
        sh[threadIdx.x] += t;
        __syncthreads();
    }
    if (g < NN) g_rowptr[g] = sh[threadIdx.x] - v;  // exclusive
    if (threadIdx.x == SCAN_CHUNK - 1) g_bsum[blockIdx.x] = sh[SCAN_CHUNK - 1];
}

__global__ void scan2_k() {
    if (threadIdx.x == 0) {
        int acc = 0;
        for (int i = 0; i < NBLK_SCAN; i++) {
            int t = g_bsum[i];
            g_bsum[i] = acc;
            acc += t;
        }
    }
}

__global__ void scan3_k() {
    int g = blockIdx.x * SCAN_CHUNK + threadIdx.x;
    if (g < NN) g_rowptr[g] += g_bsum[blockIdx.x];
}

// ---------------- place edges into CSR with precomputed norm ----------------
__global__ void place_k(const void* __restrict__ ei) {
    int e = blockIdx.x * blockDim.x + threadIdx.x;
    if (e >= EE) return;
    int r = edge_val(ei, e);
    int c = edge_val(ei, (long long)EE + e);
    float dr = fmaxf((float)g_deg[r], 1.0f);
    float dc = fmaxf((float)g_deg[c], 1.0f);
    float nr = rsqrtf(dr * dc);
    int pos = g_rowptr[r] + atomicAdd(&g_cursor[r], 1);
    g_meta[pos] = make_int2(c, __float_as_int(nr));
}

// ---------------- fused layer: CSR pull + residual + L2-normalize + out ----------------
// One warp per node; 2 floats per lane (64 dims / 32 lanes). No atomics.
// src selects ping-pong buffer: 0 => read g_x0 write g_x1, 1 => read g_x1 write g_x0.
__global__ void layer_k(int src, float* __restrict__ out, float scale) {
    int gw = (blockIdx.x * blockDim.x + threadIdx.x) >> 5;
    int lane = threadIdx.x & 31;
    if (gw >= NN) return;

    const float* xin = src ? g_x1 : g_x0;
    float* xout = src ? g_x0 : g_x1;

    int start = g_rowptr[gw];
    int end = (gw + 1 < NN) ? g_rowptr[gw + 1] : EE;

    float ax = 0.0f, ay = 0.0f;
    for (int base = start; base < end; base += 32) {
        int n = min(32, end - base);
        int2 meta = make_int2(0, 0);
        if (lane < n) meta = __ldg(&g_meta[base + lane]);
        for (int j = 0; j < n; j++) {
            int c = __shfl_sync(0xffffffffu, meta.x, j);
            float nr = __int_as_float(__shfl_sync(0xffffffffu, meta.y, j));
            float2 v = __ldg((const float2*)&xin[c * DD + lane * 2]);
            ax += nr * v.x;
            ay += nr * v.y;
        }
    }

    int bidx = gw * DD + lane * 2;
    float2 o = *(float2*)&out[bidx];
    float vx = ax + o.x;
    float vy = ay + o.y;
    float ss = vx * vx + vy * vy;
#pragma unroll
    for (int m = 16; m; m >>= 1) ss += __shfl_xor_sync(0xffffffffu, ss, m);
    float s = 1.0f / fmaxf(sqrtf(ss), 1e-12f);
    vx *= s;
    vy *= s;
    *(float2*)&xout[bidx] = make_float2(vx, vy);
    *(float2*)&out[bidx] = make_float2((o.x + vx) * scale, (o.y + vy) * scale);
}

// ---------------- launch (kernel launches ONLY — no other CUDA APIs) ----------------
extern "C" void kernel_launch(void* const* d_in, const int* in_sizes, int n_in,
                              void* d_out, int out_size) {
    int ei_idx = 0, emb_idx = 1;
    if (in_sizes[0] == NN * DD) { ei_idx = 1; emb_idx = 0; }
    const void* ei = d_in[ei_idx];
    const float* emb = (const float*)d_in[emb_idx];
    float* out = (float*)d_out;

    detect_k<<<1, 256>>>((const unsigned*)ei);
    init_k<<<(NN * DD + 255) / 256, 256>>>(emb, out);
    hist_k<<<(EE + 255) / 256, 256>>>(ei);
    scan1_k<<<NBLK_SCAN, SCAN_CHUNK>>>();
    scan2_k<<<1, 32>>>();
    scan3_k<<<NBLK_SCAN, SCAN_CHUNK>>>();
    place_k<<<(EE + 255) / 256, 256>>>(ei);

    const int node_blocks = (NN * 32 + 255) / 256;  // 12500
    layer_k<<<node_blocks, 256>>>(0, out, 1.0f);
    layer_k<<<node_blocks, 256>>>(1, out, 1.0f);
    layer_k<<<node_blocks, 256>>>(0, out, 0.25f);
}

// round 7
// speedup vs baseline: 1.6689x; 1.1706x over previous
#include <cuda_runtime.h>
#include <cuda_fp16.h>

#define NN 100000
#define DD 64
#define HD 32   // half2 elements per node row
#define EE 1200000
#define SCAN_CHUNK 1024
#define NBLK_SCAN ((NN + SCAN_CHUNK - 1) / SCAN_CHUNK)  // 98

// ---------------- scratch (static device globals — allowed) ----------------
__device__ int     g_deg[NN];      // col-degree
__device__ int     g_cnt[NN];      // row counts for CSR
__device__ int     g_rowptr[NN];   // exclusive scan of g_cnt
__device__ int     g_cursor[NN];   // placement cursors (pre-seeded to rowptr)
__device__ int     g_bsum[NBLK_SCAN];
__device__ int2    g_meta[EE];     // (col, norm-bits) sorted by row
__device__ __half2 g_x0[NN * HD];
__device__ __half2 g_x1[NN * HD];
__device__ int     g_is64;

// ---------------- dtype detection: int64 vs int32 edge_index ----------------
// For nonnegative int64 < 2^31, every odd 32-bit word (high half) is 0.
__global__ void detect_k(const unsigned* __restrict__ w) {
    __shared__ int nz;
    if (threadIdx.x == 0) nz = 0;
    __syncthreads();
    int cnt = 0;
    const int S = 8192;
    const int stride = (2 * EE) / S;
    for (int i = threadIdx.x; i < S; i += blockDim.x) {
        long long idx = ((long long)i * stride) | 1;  // odd 32-bit word
        if (w[idx] != 0u) cnt++;
    }
    atomicAdd(&nz, cnt);
    __syncthreads();
    if (threadIdx.x == 0) g_is64 = (nz == 0) ? 1 : 0;
}

__device__ __forceinline__ int edge_val(const void* ei, long long idx) {
    if (g_is64) return (int)((const long long*)ei)[idx];
    return ((const int*)ei)[idx];
}

// ---------------- init: x0 = half(emb); out = emb; zero deg/cnt ----------------
__global__ void init_k(const float* __restrict__ emb, float* __restrict__ out) {
    int i = blockIdx.x * blockDim.x + threadIdx.x;   // over NN*HD float2 pairs
    if (i < NN * HD) {
        float2 e = ((const float2*)emb)[i];
        g_x0[i] = __floats2half2_rn(e.x, e.y);
        ((float2*)out)[i] = e;
    }
    if (i < NN) {
        g_deg[i] = 0;
        g_cnt[i] = 0;
    }
}

// ---------------- histograms: col-degree + row counts ----------------
__global__ void hist_k(const void* __restrict__ ei) {
    int e = blockIdx.x * blockDim.x + threadIdx.x;
    if (e >= EE) return;
    int r = edge_val(ei, e);
    int c = edge_val(ei, (long long)EE + e);
    atomicAdd(&g_deg[c], 1);
    atomicAdd(&g_cnt[r], 1);
}

// ---------------- scan: warp-shuffle version ----------------
__global__ void scan1_k() {
    __shared__ int wsum[32];
    int g = blockIdx.x * SCAN_CHUNK + threadIdx.x;
    int v = (g < NN) ? g_cnt[g] : 0;
    int lane = threadIdx.x & 31, wid = threadIdx.x >> 5;
    int x = v;
#pragma unroll
    for (int off = 1; off < 32; off <<= 1) {
        int t = __shfl_up_sync(0xffffffffu, x, off);
        if (lane >= off) x += t;
    }
    if (lane == 31) wsum[wid] = x;
    __syncthreads();
    if (wid == 0) {
        int s = wsum[lane];
#pragma unroll
        for (int off = 1; off < 32; off <<= 1) {
            int t = __shfl_up_sync(0xffffffffu, s, off);
            if (lane >= off) s += t;
        }
        wsum[lane] = s;
    }
    __syncthreads();
    int incl = x + (wid ? wsum[wid - 1] : 0);
    if (g < NN) g_rowptr[g] = incl - v;  // exclusive
    if (threadIdx.x == SCAN_CHUNK - 1) g_bsum[blockIdx.x] = incl;
}

__global__ void scan2_k() {
    if (threadIdx.x == 0) {
        int acc = 0;
        for (int i = 0; i < NBLK_SCAN; i++) {
            int t = g_bsum[i];
            g_bsum[i] = acc;
            acc += t;
        }
    }
}

__global__ void scan3_k() {
    int g = blockIdx.x * SCAN_CHUNK + threadIdx.x;
    if (g < NN) {
        int p = g_rowptr[g] + g_bsum[blockIdx.x];
        g_rowptr[g] = p;
        g_cursor[g] = p;   // pre-seed placement cursor
    }
}

// ---------------- place edges into CSR with precomputed norm ----------------
__global__ void place_k(const void* __restrict__ ei) {
    int e = blockIdx.x * blockDim.x + threadIdx.x;
    if (e >= EE) return;
    int r = edge_val(ei, e);
    int c = edge_val(ei, (long long)EE + e);
    float dr = fmaxf((float)g_deg[r], 1.0f);
    float dc = fmaxf((float)g_deg[c], 1.0f);
    float nr = rsqrtf(dr * dc);
    int pos = atomicAdd(&g_cursor[r], 1);
    g_meta[pos] = make_int2(c, __float_as_int(nr));
}

// ---------------- fused layer: CSR pull (fp16 gather, fp32 accum) ----------------
// One warp per node; 2 dims per lane. No atomics.
__global__ void layer_k(int src, float* __restrict__ out, float scale) {
    int gw = (blockIdx.x * blockDim.x + threadIdx.x) >> 5;
    int lane = threadIdx.x & 31;
    if (gw >= NN) return;

    const __half2* xin = src ? g_x1 : g_x0;
    __half2* xout = src ? g_x0 : g_x1;

    int start = g_rowptr[gw];
    int end = (gw + 1 < NN) ? g_rowptr[gw + 1] : EE;

    float ax = 0.0f, ay = 0.0f;
    for (int base = start; base < end; base += 32) {
        int n = min(32, end - base);
        int2 meta = make_int2(0, 0);
        if (lane < n) meta = __ldg(&g_meta[base + lane]);
        for (int j = 0; j < n; j++) {
            int c = __shfl_sync(0xffffffffu, meta.x, j);
            float nr = __int_as_float(__shfl_sync(0xffffffffu, meta.y, j));
            float2 v = __half22float2(__ldg(&xin[c * HD + lane]));
            ax += nr * v.x;
            ay += nr * v.y;
        }
    }

    int bidx = gw * HD + lane;                 // float2 / half2 index
    float2 o = ((float2*)out)[bidx];
    float vx = ax + o.x;
    float vy = ay + o.y;
    float ss = vx * vx + vy * vy;
#pragma unroll
    for (int m = 16; m; m >>= 1) ss += __shfl_xor_sync(0xffffffffu, ss, m);
    float s = 1.0f / fmaxf(sqrtf(ss), 1e-12f);
    vx *= s;
    vy *= s;
    xout[bidx] = __floats2half2_rn(vx, vy);
    ((float2*)out)[bidx] = make_float2((o.x + vx) * scale, (o.y + vy) * scale);
}

// ---------------- launch (kernel launches ONLY) ----------------
extern "C" void kernel_launch(void* const* d_in, const int* in_sizes, int n_in,
                              void* d_out, int out_size) {
    int ei_idx = 0, emb_idx = 1;
    if (in_sizes[0] == NN * DD) { ei_idx = 1; emb_idx = 0; }
    const void* ei = d_in[ei_idx];
    const float* emb = (const float*)d_in[emb_idx];
    float* out = (float*)d_out;

    detect_k<<<1, 1024>>>((const unsigned*)ei);
    init_k<<<(NN * HD + 255) / 256, 256>>>(emb, out);
    hist_k<<<(EE + 255) / 256, 256>>>(ei);
    scan1_k<<<NBLK_SCAN, SCAN_CHUNK>>>();
    scan2_k<<<1, 32>>>();
    scan3_k<<<NBLK_SCAN, SCAN_CHUNK>>>();
    place_k<<<(EE + 255) / 256, 256>>>(ei);

    const int node_blocks = (NN * 32 + 255) / 256;  // 12500
    layer_k<<<node_blocks, 256>>>(0, out, 1.0f);
    layer_k<<<node_blocks, 256>>>(1, out, 1.0f);
    layer_k<<<node_blocks, 256>>>(0, out, 0.25f);
}

// round 8
// speedup vs baseline: 1.7483x; 1.0476x over previous
#include <cuda_runtime.h>
#include <cuda_fp16.h>

#define NN 100000
#define DD 64
#define HD 32   // half2 elements per node row
#define EE 1200000
#define SCAN_CHUNK 1024
#define NBLK_SCAN ((NN + SCAN_CHUNK - 1) / SCAN_CHUNK)  // 98

// ---------------- scratch (static device globals — allowed) ----------------
__device__ int     g_deg[NN];      // col-degree
__device__ int     g_cnt[NN];      // row counts for CSR
__device__ int     g_rowptr[NN];   // exclusive scan of g_cnt
__device__ int     g_cursor[NN];   // placement cursors (pre-seeded)
__device__ int     g_bsum[NBLK_SCAN];
__device__ int2    g_meta[EE];     // (col, norm-bits) sorted by row
__device__ __half2 g_x0[NN * HD];
__device__ __half2 g_x1[NN * HD];
__device__ int     g_is64;

// ---------------- init + dtype detect (block 0 samples the edge array) ----------------
// For nonnegative int64 < 2^31, every odd 32-bit word (high half) is 0.
__global__ void initdet_k(const unsigned* __restrict__ ei_words,
                          const float* __restrict__ emb, float* __restrict__ out) {
    int i = blockIdx.x * blockDim.x + threadIdx.x;
    if (i < NN * HD) {
        float2 e = ((const float2*)emb)[i];
        g_x0[i] = __floats2half2_rn(e.x, e.y);
        ((float2*)out)[i] = e;
    }
    if (i < NN) {
        g_deg[i] = 0;
        g_cnt[i] = 0;
    }
    if (blockIdx.x == 0) {
        __shared__ int nz;
        if (threadIdx.x == 0) nz = 0;
        __syncthreads();
        int cnt = 0;
        const int S = 8192;
        const int stride = (2 * EE) / S;
        for (int s = threadIdx.x; s < S; s += blockDim.x) {
            long long idx = ((long long)s * stride) | 1;  // odd 32-bit word
            if (ei_words[idx] != 0u) cnt++;
        }
        atomicAdd(&nz, cnt);
        __syncthreads();
        if (threadIdx.x == 0) g_is64 = (nz == 0) ? 1 : 0;
    }
}

__device__ __forceinline__ int edge_val(const void* ei, long long idx) {
    if (g_is64) return (int)((const long long*)ei)[idx];
    return ((const int*)ei)[idx];
}

// ---------------- histograms: col-degree + row counts ----------------
__global__ void hist_k(const void* __restrict__ ei) {
    int e = blockIdx.x * blockDim.x + threadIdx.x;
    if (e >= EE) return;
    int r = edge_val(ei, e);
    int c = edge_val(ei, (long long)EE + e);
    atomicAdd(&g_deg[c], 1);
    atomicAdd(&g_cnt[r], 1);
}

// ---------------- scan step 1: per-block exclusive scan (warp shuffles) ----------------
__global__ void scan1_k() {
    __shared__ int wsum[32];
    int g = blockIdx.x * SCAN_CHUNK + threadIdx.x;
    int v = (g < NN) ? g_cnt[g] : 0;
    int lane = threadIdx.x & 31, wid = threadIdx.x >> 5;
    int x = v;
#pragma unroll
    for (int off = 1; off < 32; off <<= 1) {
        int t = __shfl_up_sync(0xffffffffu, x, off);
        if (lane >= off) x += t;
    }
    if (lane == 31) wsum[wid] = x;
    __syncthreads();
    if (wid == 0) {
        int s = wsum[lane];
#pragma unroll
        for (int off = 1; off < 32; off <<= 1) {
            int t = __shfl_up_sync(0xffffffffu, s, off);
            if (lane >= off) s += t;
        }
        wsum[lane] = s;
    }
    __syncthreads();
    int incl = x + (wid ? wsum[wid - 1] : 0);
    if (g < NN) g_rowptr[g] = incl - v;  // block-local exclusive
    if (threadIdx.x == SCAN_CHUNK - 1) g_bsum[blockIdx.x] = incl;
}

// ---------------- scan step 2: each block reduces prior block sums, applies offset,
//                  seeds cursor ----------------
__global__ void scan3_k() {
    __shared__ int sh[128];
    int t = threadIdx.x;
    if (t < 128) sh[t] = (t < blockIdx.x && t < NBLK_SCAN) ? g_bsum[t] : 0;
    __syncthreads();
#pragma unroll
    for (int off = 64; off; off >>= 1) {
        if (t < off) sh[t] += sh[t + off];
        __syncthreads();
    }
    int offset = sh[0];
    int g = blockIdx.x * SCAN_CHUNK + t;
    if (g < NN) {
        int p = g_rowptr[g] + offset;
        g_rowptr[g] = p;
        g_cursor[g] = p;
    }
}

// ---------------- place edges into CSR with precomputed norm ----------------
__global__ void place_k(const void* __restrict__ ei) {
    int e = blockIdx.x * blockDim.x + threadIdx.x;
    if (e >= EE) return;
    int r = edge_val(ei, e);
    int c = edge_val(ei, (long long)EE + e);
    float dr = fmaxf((float)__ldg(&g_deg[r]), 1.0f);
    float dc = fmaxf((float)__ldg(&g_deg[c]), 1.0f);
    float nr = rsqrtf(dr * dc);
    int pos = atomicAdd(&g_cursor[r], 1);
    g_meta[pos] = make_int2(c, __float_as_int(nr));
}

// ---------------- fused layer: CSR pull (fp16 gather, fp32 accum) ----------------
// One warp per node; 2 dims per lane. No atomics.
__global__ void layer_k(int src, float* __restrict__ out, float scale) {
    int gw = (blockIdx.x * blockDim.x + threadIdx.x) >> 5;
    int lane = threadIdx.x & 31;
    if (gw >= NN) return;

    const __half2* xin = src ? g_x1 : g_x0;
    __half2* xout = src ? g_x0 : g_x1;

    int start = g_rowptr[gw];
    int end = (gw + 1 < NN) ? g_rowptr[gw + 1] : EE;

    float ax = 0.0f, ay = 0.0f;
    for (int base = start; base < end; base += 32) {
        int n = min(32, end - base);
        int2 meta = make_int2(0, 0);
        if (lane < n) meta = __ldg(&g_meta[base + lane]);
        for (int j = 0; j < n; j++) {
            int c = __shfl_sync(0xffffffffu, meta.x, j);
            float nr = __int_as_float(__shfl_sync(0xffffffffu, meta.y, j));
            float2 v = __half22float2(__ldg(&xin[c * HD + lane]));
            ax += nr * v.x;
            ay += nr * v.y;
        }
    }

    int bidx = gw * HD + lane;                 // float2 / half2 index
    float2 o = ((float2*)out)[bidx];
    float vx = ax + o.x;
    float vy = ay + o.y;
    float ss = vx * vx + vy * vy;
#pragma unroll
    for (int m = 16; m; m >>= 1) ss += __shfl_xor_sync(0xffffffffu, ss, m);
    float s = 1.0f / fmaxf(sqrtf(ss), 1e-12f);
    vx *= s;
    vy *= s;
    xout[bidx] = __floats2half2_rn(vx, vy);
    ((float2*)out)[bidx] = make_float2((o.x + vx) * scale, (o.y + vy) * scale);
}

// ---------------- launch (kernel launches ONLY) ----------------
// Launch order puts the first layer_k at index 5 so ncu (-s 5 -c 1) captures it.
extern "C" void kernel_launch(void* const* d_in, const int* in_sizes, int n_in,
                              void* d_out, int out_size) {
    int ei_idx = 0, emb_idx = 1;
    if (in_sizes[0] == NN * DD) { ei_idx = 1; emb_idx = 0; }
    const void* ei = d_in[ei_idx];
    const float* emb = (const float*)d_in[emb_idx];
    float* out = (float*)d_out;

    initdet_k<<<(NN * HD + 255) / 256, 256>>>((const unsigned*)ei, emb, out);  // 0
    hist_k<<<(EE + 255) / 256, 256>>>(ei);                                      // 1
    scan1_k<<<NBLK_SCAN, SCAN_CHUNK>>>();                                       // 2
    scan3_k<<<NBLK_SCAN, SCAN_CHUNK>>>();                                       // 3
    place_k<<<(EE + 255) / 256, 256>>>(ei);                                     // 4

    const int node_blocks = (NN * 32 + 255) / 256;  // 12500
    layer_k<<<node_blocks, 256>>>(0, out, 1.0f);                                // 5 <- ncu
    layer_k<<<node_blocks, 256>>>(1, out, 1.0f);                                // 6
    layer_k<<<node_blocks, 256>>>(0, out, 0.25f);                               // 7
}

// round 9
// speedup vs baseline: 1.8586x; 1.0631x over previous
#include <cuda_runtime.h>
#include <cuda_fp16.h>

#define NN 100000
#define DD 64
#define HD 32   // half2 elements per node row
#define EE 1200000
#define SCAN_CHUNK 1024
#define NBLK_SCAN ((NN + SCAN_CHUNK - 1) / SCAN_CHUNK)  // 98

// ---------------- scratch (static device globals — allowed) ----------------
__device__ int     g_deg[NN];      // col-degree
__device__ int     g_cnt[NN];      // row counts for CSR
__device__ int     g_rowptr[NN];   // exclusive scan of g_cnt
__device__ int     g_cursor[NN];   // placement cursors (pre-seeded)
__device__ int     g_bsum[NBLK_SCAN];
__device__ int2    g_meta[EE];     // (col, norm-bits) sorted by row
__device__ __half2 g_x0[NN * HD];
__device__ __half2 g_x1[NN * HD];
__device__ int     g_is64;

// ---------------- init + dtype detect (block 0 samples the edge array) ----------------
// For nonnegative int64 < 2^31, every odd 32-bit word (high half) is 0.
__global__ void initdet_k(const unsigned* __restrict__ ei_words,
                          const float* __restrict__ emb, float* __restrict__ out) {
    int i = blockIdx.x * blockDim.x + threadIdx.x;
    if (i < NN * HD) {
        float2 e = ((const float2*)emb)[i];
        g_x0[i] = __floats2half2_rn(e.x, e.y);
        ((float2*)out)[i] = e;
    }
    if (i < NN) {
        g_deg[i] = 0;
        g_cnt[i] = 0;
    }
    if (blockIdx.x == 0) {
        __shared__ int nz;
        if (threadIdx.x == 0) nz = 0;
        __syncthreads();
        int cnt = 0;
        const int S = 8192;
        const int stride = (2 * EE) / S;
        for (int s = threadIdx.x; s < S; s += blockDim.x) {
            long long idx = ((long long)s * stride) | 1;  // odd 32-bit word
            if (ei_words[idx] != 0u) cnt++;
        }
        atomicAdd(&nz, cnt);
        __syncthreads();
        if (threadIdx.x == 0) g_is64 = (nz == 0) ? 1 : 0;
    }
}

__device__ __forceinline__ int edge_val(const void* ei, long long idx) {
    if (g_is64) return (int)((const long long*)ei)[idx];
    return ((const int*)ei)[idx];
}

// ---------------- histograms: col-degree + row counts ----------------
__global__ void hist_k(const void* __restrict__ ei) {
    int e = blockIdx.x * blockDim.x + threadIdx.x;
    if (e >= EE) return;
    int r = edge_val(ei, e);
    int c = edge_val(ei, (long long)EE + e);
    atomicAdd(&g_deg[c], 1);
    atomicAdd(&g_cnt[r], 1);
}

// ---------------- scan step 1: per-block exclusive scan (warp shuffles) ----------------
__global__ void scan1_k() {
    __shared__ int wsum[32];
    int g = blockIdx.x * SCAN_CHUNK + threadIdx.x;
    int v = (g < NN) ? g_cnt[g] : 0;
    int lane = threadIdx.x & 31, wid = threadIdx.x >> 5;
    int x = v;
#pragma unroll
    for (int off = 1; off < 32; off <<= 1) {
        int t = __shfl_up_sync(0xffffffffu, x, off);
        if (lane >= off) x += t;
    }
    if (lane == 31) wsum[wid] = x;
    __syncthreads();
    if (wid == 0) {
        int s = wsum[lane];
#pragma unroll
        for (int off = 1; off < 32; off <<= 1) {
            int t = __shfl_up_sync(0xffffffffu, s, off);
            if (lane >= off) s += t;
        }
        wsum[lane] = s;
    }
    __syncthreads();
    int incl = x + (wid ? wsum[wid - 1] : 0);
    if (g < NN) g_rowptr[g] = incl - v;  // block-local exclusive
    if (threadIdx.x == SCAN_CHUNK - 1) g_bsum[blockIdx.x] = incl;
}

// ---------------- scan step 2: apply block offsets, seed cursor ----------------
__global__ void scan3_k() {
    __shared__ int sh[128];
    int t = threadIdx.x;
    if (t < 128) sh[t] = (t < blockIdx.x && t < NBLK_SCAN) ? g_bsum[t] : 0;
    __syncthreads();
#pragma unroll
    for (int off = 64; off; off >>= 1) {
        if (t < off) sh[t] += sh[t + off];
        __syncthreads();
    }
    int offset = sh[0];
    int g = blockIdx.x * SCAN_CHUNK + t;
    if (g < NN) {
        int p = g_rowptr[g] + offset;
        g_rowptr[g] = p;
        g_cursor[g] = p;
    }
}

// ---------------- place edges into CSR with precomputed norm ----------------
__global__ void place_k(const void* __restrict__ ei) {
    int e = blockIdx.x * blockDim.x + threadIdx.x;
    if (e >= EE) return;
    int r = edge_val(ei, e);
    int c = edge_val(ei, (long long)EE + e);
    float dr = fmaxf((float)__ldg(&g_deg[r]), 1.0f);
    float dc = fmaxf((float)__ldg(&g_deg[c]), 1.0f);
    float nr = rsqrtf(dr * dc);
    int pos = atomicAdd(&g_cursor[r], 1);
    g_meta[pos] = make_int2(c, __float_as_int(nr));
}

// ---------------- fused layer: CSR pull (fp16 gather, fp32 accum) ----------------
// One warp per node; 2 dims per lane. No atomics.
// Inner gather loop unrolled x4: 4 independent LDGs in flight (MLP>=4).
// write_x: final layer's x output is never consumed -> skip the store.
__global__ void layer_k(int src, float* __restrict__ out, float scale, int write_x) {
    int gw = (blockIdx.x * blockDim.x + threadIdx.x) >> 5;
    int lane = threadIdx.x & 31;
    if (gw >= NN) return;

    const __half2* xin = src ? g_x1 : g_x0;
    __half2* xout = src ? g_x0 : g_x1;

    int start = g_rowptr[gw];
    int end = (gw + 1 < NN) ? g_rowptr[gw + 1] : EE;

    float ax = 0.0f, ay = 0.0f;
    for (int base = start; base < end; base += 32) {
        int n = min(32, end - base);
        int2 meta = make_int2(0, 0);
        if (lane < n) meta = __ldg(&g_meta[base + lane]);
        int j = 0;
        for (; j + 4 <= n; j += 4) {
            int c0 = __shfl_sync(0xffffffffu, meta.x, j);
            int c1 = __shfl_sync(0xffffffffu, meta.x, j + 1);
            int c2 = __shfl_sync(0xffffffffu, meta.x, j + 2);
            int c3 = __shfl_sync(0xffffffffu, meta.x, j + 3);
            float n0 = __int_as_float(__shfl_sync(0xffffffffu, meta.y, j));
            float n1 = __int_as_float(__shfl_sync(0xffffffffu, meta.y, j + 1));
            float n2 = __int_as_float(__shfl_sync(0xffffffffu, meta.y, j + 2));
            float n3 = __int_as_float(__shfl_sync(0xffffffffu, meta.y, j + 3));
            __half2 h0 = __ldg(&xin[c0 * HD + lane]);
            __half2 h1 = __ldg(&xin[c1 * HD + lane]);
            __half2 h2 = __ldg(&xin[c2 * HD + lane]);
            __half2 h3 = __ldg(&xin[c3 * HD + lane]);
            float2 v0 = __half22float2(h0);
            float2 v1 = __half22float2(h1);
            float2 v2 = __half22float2(h2);
            float2 v3 = __half22float2(h3);
            ax += n0 * v0.x;  ay += n0 * v0.y;
            ax += n1 * v1.x;  ay += n1 * v1.y;
            ax += n2 * v2.x;  ay += n2 * v2.y;
            ax += n3 * v3.x;  ay += n3 * v3.y;
        }
        for (; j < n; j++) {
            int c = __shfl_sync(0xffffffffu, meta.x, j);
            float nr = __int_as_float(__shfl_sync(0xffffffffu, meta.y, j));
            float2 v = __half22float2(__ldg(&xin[c * HD + lane]));
            ax += nr * v.x;
            ay += nr * v.y;
        }
    }

    int bidx = gw * HD + lane;                 // float2 / half2 index
    float2 o = ((float2*)out)[bidx];
    float vx = ax + o.x;
    float vy = ay + o.y;
    float ss = vx * vx + vy * vy;
#pragma unroll
    for (int m = 16; m; m >>= 1) ss += __shfl_xor_sync(0xffffffffu, ss, m);
    float s = 1.0f / fmaxf(sqrtf(ss), 1e-12f);
    vx *= s;
    vy *= s;
    if (write_x) xout[bidx] = __floats2half2_rn(vx, vy);
    ((float2*)out)[bidx] = make_float2((o.x + vx) * scale, (o.y + vy) * scale);
}

// ---------------- launch (kernel launches ONLY) ----------------
extern "C" void kernel_launch(void* const* d_in, const int* in_sizes, int n_in,
                              void* d_out, int out_size) {
    int ei_idx = 0, emb_idx = 1;
    if (in_sizes[0] == NN * DD) { ei_idx = 1; emb_idx = 0; }
    const void* ei = d_in[ei_idx];
    const float* emb = (const float*)d_in[emb_idx];
    float* out = (float*)d_out;

    initdet_k<<<(NN * HD + 255) / 256, 256>>>((const unsigned*)ei, emb, out);
    hist_k<<<(EE + 255) / 256, 256>>>(ei);
    scan1_k<<<NBLK_SCAN, SCAN_CHUNK>>>();
    scan3_k<<<NBLK_SCAN, SCAN_CHUNK>>>();
    place_k<<<(EE + 255) / 256, 256>>>(ei);

    const int node_blocks = (NN * 32 + 255) / 256;  // 12500
    layer_k<<<node_blocks, 256>>>(0, out, 1.0f, 1);
    layer_k<<<node_blocks, 256>>>(1, out, 1.0f, 1);
    layer_k<<<node_blocks, 256>>>(0, out, 0.25f, 0);
}

// round 10
// speedup vs baseline: 1.8590x; 1.0002x over previous
#include <cuda_runtime.h>
#include <cuda_fp16.h>

#define NN 100000
#define DD 64
#define HD 32   // half2 elements per node row
#define EE 1200000
#define SCAN_CHUNK 1024
#define NBLK_SCAN ((NN + SCAN_CHUNK - 1) / SCAN_CHUNK)  // 98

// ---------------- scratch (static device globals — allowed) ----------------
__device__ int     g_deg[NN];      // col-degree
__device__ int     g_cnt[NN];      // row counts for CSR
__device__ int     g_rowptr[NN];   // exclusive scan of g_cnt
__device__ int     g_cursor[NN];   // placement cursors (pre-seeded)
__device__ float   g_invsq[NN];    // rsqrt(max(deg,1))
__device__ int     g_bsum[NBLK_SCAN];
__device__ int     g_col[EE];      // col only, sorted by row
__device__ __half2 g_x0[NN * HD];  // pre-scaled features: invsq[node]*x[node]
__device__ __half2 g_x1[NN * HD];
__device__ int     g_is64;

// ---------------- init + dtype detect (block 0 samples the edge array) ----------------
// For nonnegative int64 < 2^31, every odd 32-bit word (high half) is 0.
__global__ void initdet_k(const unsigned* __restrict__ ei_words,
                          const float* __restrict__ emb, float* __restrict__ out) {
    int i = blockIdx.x * blockDim.x + threadIdx.x;
    if (i < NN * HD) {
        ((float2*)out)[i] = ((const float2*)emb)[i];
    }
    if (i < NN) {
        g_deg[i] = 0;
        g_cnt[i] = 0;
    }
    if (blockIdx.x == 0) {
        __shared__ int nz;
        if (threadIdx.x == 0) nz = 0;
        __syncthreads();
        int cnt = 0;
        const int S = 8192;
        const int stride = (2 * EE) / S;
        for (int s = threadIdx.x; s < S; s += blockDim.x) {
            long long idx = ((long long)s * stride) | 1;  // odd 32-bit word
            if (ei_words[idx] != 0u) cnt++;
        }
        atomicAdd(&nz, cnt);
        __syncthreads();
        if (threadIdx.x == 0) g_is64 = (nz == 0) ? 1 : 0;
    }
}

__device__ __forceinline__ int edge_val(const void* ei, long long idx) {
    if (g_is64) return (int)((const long long*)ei)[idx];
    return ((const int*)ei)[idx];
}

// ---------------- histograms: col-degree + row counts ----------------
__global__ void hist_k(const void* __restrict__ ei) {
    int e = blockIdx.x * blockDim.x + threadIdx.x;
    if (e >= EE) return;
    int r = edge_val(ei, e);
    int c = edge_val(ei, (long long)EE + e);
    atomicAdd(&g_deg[c], 1);
    atomicAdd(&g_cnt[r], 1);
}

// ---------------- scan step 1: per-block exclusive scan (warp shuffles) ----------------
__global__ void scan1_k() {
    __shared__ int wsum[32];
    int g = blockIdx.x * SCAN_CHUNK + threadIdx.x;
    int v = (g < NN) ? g_cnt[g] : 0;
    int lane = threadIdx.x & 31, wid = threadIdx.x >> 5;
    int x = v;
#pragma unroll
    for (int off = 1; off < 32; off <<= 1) {
        int t = __shfl_up_sync(0xffffffffu, x, off);
        if (lane >= off) x += t;
    }
    if (lane == 31) wsum[wid] = x;
    __syncthreads();
    if (wid == 0) {
        int s = wsum[lane];
#pragma unroll
        for (int off = 1; off < 32; off <<= 1) {
            int t = __shfl_up_sync(0xffffffffu, s, off);
            if (lane >= off) s += t;
        }
        wsum[lane] = s;
    }
    __syncthreads();
    int incl = x + (wid ? wsum[wid - 1] : 0);
    if (g < NN) g_rowptr[g] = incl - v;  // block-local exclusive
    if (threadIdx.x == SCAN_CHUNK - 1) g_bsum[blockIdx.x] = incl;
}

// ---------------- scan step 2: apply block offsets, seed cursor, compute invsq ----------------
__global__ void scan3_k() {
    __shared__ int sh[128];
    int t = threadIdx.x;
    if (t < 128) sh[t] = (t < blockIdx.x && t < NBLK_SCAN) ? g_bsum[t] : 0;
    __syncthreads();
#pragma unroll
    for (int off = 64; off; off >>= 1) {
        if (t < off) sh[t] += sh[t + off];
        __syncthreads();
    }
    int offset = sh[0];
    int g = blockIdx.x * SCAN_CHUNK + t;
    if (g < NN) {
        int p = g_rowptr[g] + offset;
        g_rowptr[g] = p;
        g_cursor[g] = p;
        g_invsq[g] = rsqrtf(fmaxf((float)g_deg[g], 1.0f));
    }
}

// ---------------- scale: x0 = half(invsq[node] * emb) ----------------
__global__ void scale_k(const float* __restrict__ emb) {
    int i = blockIdx.x * blockDim.x + threadIdx.x;
    if (i >= NN * HD) return;
    float isr = g_invsq[i >> 5];
    float2 e = ((const float2*)emb)[i];
    g_x0[i] = __floats2half2_rn(e.x * isr, e.y * isr);
}

// ---------------- place edges into CSR (col only; norm folded into x) ----------------
__global__ void place_k(const void* __restrict__ ei) {
    int e = blockIdx.x * blockDim.x + threadIdx.x;
    if (e >= EE) return;
    int r = edge_val(ei, e);
    int c = edge_val(ei, (long long)EE + e);
    int pos = atomicAdd(&g_cursor[r], 1);
    g_col[pos] = c;
}

// ---------------- fused layer: CSR pull of pre-scaled fp16 features ----------------
// One warp per node; 2 dims per lane. Inner loop: 1 shfl + 1 LDG + 2 FADD per edge.
// msg = invsq[row] * sum(x'[col]);  next-layer store is pre-scaled by invsq[row].
__global__ void layer_k(int src, float* __restrict__ out, float scale, int write_x) {
    int gw = (blockIdx.x * blockDim.x + threadIdx.x) >> 5;
    int lane = threadIdx.x & 31;
    if (gw >= NN) return;

    const __half2* xin = src ? g_x1 : g_x0;
    __half2* xout = src ? g_x0 : g_x1;

    int start = g_rowptr[gw];
    int end = (gw + 1 < NN) ? g_rowptr[gw + 1] : EE;

    float ax = 0.0f, ay = 0.0f;
    for (int base = start; base < end; base += 32) {
        int n = min(32, end - base);
        int col = 0;
        if (lane < n) col = __ldg(&g_col[base + lane]);
        int j = 0;
        for (; j + 4 <= n; j += 4) {
            int c0 = __shfl_sync(0xffffffffu, col, j);
            int c1 = __shfl_sync(0xffffffffu, col, j + 1);
            int c2 = __shfl_sync(0xffffffffu, col, j + 2);
            int c3 = __shfl_sync(0xffffffffu, col, j + 3);
            __half2 h0 = __ldg(&xin[c0 * HD + lane]);
            __half2 h1 = __ldg(&xin[c1 * HD + lane]);
            __half2 h2 = __ldg(&xin[c2 * HD + lane]);
            __half2 h3 = __ldg(&xin[c3 * HD + lane]);
            float2 v0 = __half22float2(h0);
            float2 v1 = __half22float2(h1);
            float2 v2 = __half22float2(h2);
            float2 v3 = __half22float2(h3);
            ax += v0.x + v1.x;  ay += v0.y + v1.y;
            ax += v2.x + v3.x;  ay += v2.y + v3.y;
        }
        for (; j < n; j++) {
            int c = __shfl_sync(0xffffffffu, col, j);
            float2 v = __half22float2(__ldg(&xin[c * HD + lane]));
            ax += v.x;
            ay += v.y;
        }
    }

    float isr = g_invsq[gw];
    ax *= isr;
    ay *= isr;

    int bidx = gw * HD + lane;                 // float2 / half2 index
    float2 o = ((float2*)out)[bidx];
    float vx = ax + o.x;
    float vy = ay + o.y;
    float ss = vx * vx + vy * vy;
#pragma unroll
    for (int m = 16; m; m >>= 1) ss += __shfl_xor_sync(0xffffffffu, ss, m);
    float s = 1.0f / fmaxf(sqrtf(ss), 1e-12f);
    vx *= s;
    vy *= s;
    if (write_x) xout[bidx] = __floats2half2_rn(vx * isr, vy * isr);
    ((float2*)out)[bidx] = make_float2((o.x + vx) * scale, (o.y + vy) * scale);
}

// ---------------- launch (kernel launches ONLY) ----------------
extern "C" void kernel_launch(void* const* d_in, const int* in_sizes, int n_in,
                              void* d_out, int out_size) {
    int ei_idx = 0, emb_idx = 1;
    if (in_sizes[0] == NN * DD) { ei_idx = 1; emb_idx = 0; }
    const void* ei = d_in[ei_idx];
    const float* emb = (const float*)d_in[emb_idx];
    float* out = (float*)d_out;

    initdet_k<<<(NN * HD + 255) / 256, 256>>>((const unsigned*)ei, emb, out);
    hist_k<<<(EE + 255) / 256, 256>>>(ei);
    scan1_k<<<NBLK_SCAN, SCAN_CHUNK>>>();
    scan3_k<<<NBLK_SCAN, SCAN_CHUNK>>>();
    scale_k<<<(NN * HD + 255) / 256, 256>>>(emb);
    place_k<<<(EE + 255) / 256, 256>>>(ei);

    const int node_blocks = (NN * 32 + 255) / 256;  // 12500
    layer_k<<<node_blocks, 256>>>(0, out, 1.0f, 1);
    layer_k<<<node_blocks, 256>>>(1, out, 1.0f, 1);
    layer_k<<<node_blocks, 256>>>(0, out, 0.25f, 0);
}